// round 7
// baseline (speedup 1.0000x reference)
#include <cuda_runtime.h>
#include <cuda_fp16.h>
#include <cstdint>

// Problem constants
constexpr int B_ = 16, T_ = 128, N_ = 64, D_ = 256, H_ = 512;
constexpr int MROWS = B_ * T_ * N_;          // 131072 flattened rows
constexpr int BT   = B_ * T_;                // 2048 attention problems
constexpr size_t BUF  = (size_t)MROWS * H_;  // 67.1M elems (q/k/v buffers)
constexpr size_t XBUF = (size_t)MROWS * D_;  // fp16 copies of x

// ---------------- scratch (device globals) ---------------------------------
__device__ __align__(16) __half g_h[6 * BUF + 2 * XBUF];
// packed fp16x2 weights: wqkv1(3*65536) wqkv2(3*65536) w1p(262144) w2p(131072)
__device__ __align__(16) uint32_t g_w[786432];

__device__ __forceinline__ uint32_t pk(float a, float b) {
    __half2 h = __floats2half2_rn(a, b);
    return *reinterpret_cast<uint32_t*>(&h);
}
__device__ __forceinline__ void st2(float* p, float v0, float v1) {
    *reinterpret_cast<float2*>(p) = make_float2(v0, v1);
}
__device__ __forceinline__ void st2(__half* p, float v0, float v1) {
    *reinterpret_cast<__half2*>(p) = __floats2half2_rn(v0, v1);
}

// mma.sync m16n8k16 fp16 in / fp32 accum, D += A*B
__device__ __forceinline__ void mma16(float* d, const uint32_t* a, const uint32_t* b) {
    asm volatile(
        "mma.sync.aligned.m16n8k16.row.col.f32.f16.f16.f32 "
        "{%0,%1,%2,%3}, {%4,%5,%6,%7}, {%8,%9}, {%0,%1,%2,%3};"
        : "+f"(d[0]), "+f"(d[1]), "+f"(d[2]), "+f"(d[3])
        : "r"(a[0]), "r"(a[1]), "r"(a[2]), "r"(a[3]),
          "r"(b[0]), "r"(b[1]));
}

__device__ __forceinline__ void cpa16(uint32_t dst_smem, const void* src) {
    asm volatile("cp.async.cg.shared.global [%0], [%1], 16;" :: "r"(dst_smem), "l"(src));
}
__device__ __forceinline__ void cpa_commit() { asm volatile("cp.async.commit_group;"); }
template<int Ngrp> __device__ __forceinline__ void cpa_wait() {
    asm volatile("cp.async.wait_group %0;" :: "n"(Ngrp));
}

// ======================= conversion pre-pass ==============================
__global__ void cvt_f2h(const float* __restrict__ src, __half* __restrict__ dst, int n4) {
    for (int i = blockIdx.x * blockDim.x + threadIdx.x; i < n4; i += gridDim.x * blockDim.x) {
        float4 v = reinterpret_cast<const float4*>(src)[i];
        reinterpret_cast<uint2*>(dst)[i] = make_uint2(pk(v.x, v.y), pk(v.z, v.w));
    }
}
// Pack ALL weights in one launch. Regions (words): 6 x 65536, 262144, 131072.
struct WSrc { const float* w[8]; };
__global__ void pack_all(WSrc ws, uint32_t* __restrict__ out) {
    constexpr int R6 = 6 * 65536;           // 393216
    constexpr int R7 = R6 + 262144;         // 655360
    constexpr int TOT = R7 + 131072;        // 786432
    for (int i = blockIdx.x * blockDim.x + threadIdx.x; i < TOT; i += gridDim.x * blockDim.x) {
        const float* W; int local;
        if (i < R6)      { W = ws.w[i >> 16];  local = i & 65535; }
        else if (i < R7) { W = ws.w[6];        local = i - R6; }
        else             { W = ws.w[7];        local = i - R7; }
        int kp = local >> 9, n = local & 511;
        out[i] = pk(W[(size_t)(2 * kp) * 512 + n], W[(size_t)(2 * kp + 1) * 512 + n]);
    }
}

// =============================== GEMM =====================================
// C[M,512] = act( alpha * (A @ B) + bias ).  A fp16 row-major [M,K],
// B pre-packed u32 k-pair words [K/2][512].
// 128x128x64 tiles, 3-stage cp.async pipeline (prefetch distance 2),
// 256 thr, 8 warps (4m x 2n).
// PROJ: blockIdx.z in [0,6): A = z<3 ? A0 : A1; B/C strided by z; alpha on z%3==0.
// SPLITA: A K-split at ksplit between A0/A1 (for concat MLP input).
constexpr int AW = 36, BW = 136;          // smem strides (words)
constexpr int A_ST = 128 * AW;            // 4608 words
constexpr int B_ST = 32 * BW;             // 4352 words
constexpr int ST_W = A_ST + B_ST;         // 8960 words / stage
constexpr int NST = 3;
constexpr size_t GEMM_SMEM = (size_t)ST_W * NST * 4;   // 107520 B

template<typename TC, bool RELU, bool SPLITA, bool PROJ>
__global__ void __launch_bounds__(256) gemm_p(
    const __half* __restrict__ A0, const __half* __restrict__ A1,
    const uint32_t* __restrict__ Bp, const float* __restrict__ bias,
    TC* __restrict__ C, int K, int ksplit, int lda,
    size_t bstride, size_t cstride, float alpha0)
{
    extern __shared__ uint32_t smem[];
    const uint32_t sm_base = (uint32_t)__cvta_generic_to_shared(smem);

    const int tid = threadIdx.x;
    const int bm  = blockIdx.y * 128;
    const int bn  = blockIdx.x * 128;
    const __half*   Az = PROJ ? (blockIdx.z < 3 ? A0 : A1) : A0;
    const uint32_t* Bz = Bp + (size_t)blockIdx.z * bstride;
    TC* Cz = C + (size_t)blockIdx.z * cstride;
    const float alpha = PROJ ? ((blockIdx.z % 3 == 0) ? alpha0 : 1.0f) : alpha0;

    const int w = tid >> 5, lane = tid & 31;
    const int wm = (w & 3) * 32, wn = (w >> 2) * 64;
    const int lr = lane >> 2, lc = lane & 3;

    float acc[2][8][4];
#pragma unroll
    for (int i = 0; i < 2; i++)
#pragma unroll
        for (int j = 0; j < 8; j++)
#pragma unroll
            for (int k = 0; k < 4; k++) acc[i][j][k] = 0.f;

    auto load_stage = [&](int s, int k0) {
        const __half* Ab = Az;
        int kl = k0;
        if (SPLITA && k0 >= ksplit) { Ab = A1; kl = k0 - ksplit; }
        uint32_t abase = sm_base + (uint32_t)(s * ST_W) * 4;
        uint32_t bbase = abase + (uint32_t)A_ST * 4;
#pragma unroll
        for (int i = 0; i < 4; i++) {
            int id = tid + i * 256;
            int r = id >> 3, q = id & 7;
            cpa16(abase + (uint32_t)(r * AW + q * 4) * 4,
                  Ab + (size_t)(bm + r) * lda + kl + q * 8);
        }
#pragma unroll
        for (int i = 0; i < 4; i++) {
            int id = tid + i * 256;
            int kp = id >> 5, j = id & 31;
            cpa16(bbase + (uint32_t)(kp * BW + j * 4) * 4,
                  Bz + (size_t)((k0 >> 1) + kp) * 512 + bn + j * 4);
        }
    };

    const int ntiles = K >> 6;
    load_stage(0, 0);  cpa_commit();
    if (ntiles > 1) load_stage(1, 64);
    cpa_commit();

    for (int t = 0; t < ntiles; t++) {
        cpa_wait<1>();
        __syncthreads();
        int tn = t + 2;
        if (tn < ntiles) load_stage(tn % NST, tn << 6);
        cpa_commit();

        const uint32_t* Ast = smem + (t % NST) * ST_W;
        const uint32_t* Bst = Ast + A_ST;
#pragma unroll
        for (int kk2 = 0; kk2 < 32; kk2 += 8) {
            uint32_t af[2][4];
#pragma unroll
            for (int mi = 0; mi < 2; mi++) {
                int r0 = wm + mi * 16 + lr;
                af[mi][0] = Ast[r0 * AW + kk2 + lc];
                af[mi][1] = Ast[(r0 + 8) * AW + kk2 + lc];
                af[mi][2] = Ast[r0 * AW + kk2 + lc + 4];
                af[mi][3] = Ast[(r0 + 8) * AW + kk2 + lc + 4];
            }
            uint32_t bf[8][2];
#pragma unroll
            for (int ni = 0; ni < 8; ni++) {
                int c0 = wn + ni * 8 + lr;
                bf[ni][0] = Bst[(kk2 + lc) * BW + c0];
                bf[ni][1] = Bst[(kk2 + lc + 4) * BW + c0];
            }
#pragma unroll
            for (int mi = 0; mi < 2; mi++)
#pragma unroll
                for (int ni = 0; ni < 8; ni++)
                    mma16(acc[mi][ni], af[mi], bf[ni]);
        }
        __syncthreads();
    }

#pragma unroll
    for (int mi = 0; mi < 2; mi++) {
#pragma unroll
        for (int ni = 0; ni < 8; ni++) {
            int row = bm + wm + mi * 16 + lr;
            int col = bn + wn + ni * 8 + lc * 2;
            float b0 = 0.f, b1 = 0.f;
            if (bias) { b0 = bias[col]; b1 = bias[col + 1]; }
            float v0 = acc[mi][ni][0] * alpha + b0;
            float v1 = acc[mi][ni][1] * alpha + b1;
            float v2 = acc[mi][ni][2] * alpha + b0;
            float v3 = acc[mi][ni][3] * alpha + b1;
            if (RELU) {
                v0 = fmaxf(v0, 0.f); v1 = fmaxf(v1, 0.f);
                v2 = fmaxf(v2, 0.f); v3 = fmaxf(v3, 0.f);
            }
            st2(Cz + (size_t)row * 512 + col, v0, v1);
            st2(Cz + (size_t)(row + 8) * 512 + col, v2, v3);
        }
    }
}

// ============================ Attention ===================================
// grid (2048, 2): y==0: a1 = softmax(q1 k2^T) v1 ; y==1: a2 = softmax(q2 k1^T) v2.
// O aliases V (per-column-chunk read-then-write, disjoint chunks).
// Phase 1: 3-stage cp.async Q/K chunk pipeline. Phase 3: reg-pipelined V LDG.
// smem: dynamic, 6 * QST words = 55296 B (opt-in via cudaFuncSetAttribute).
constexpr int QW = 36, SLD = 68, VW = 72;
constexpr int QST = 64 * QW;   // 2304 words / stage
constexpr size_t ATTN_SMEM = (size_t)6 * QST * 4;   // 55296 B

__global__ void __launch_bounds__(256) attn_kernel(
    const __half* __restrict__ q1, const __half* __restrict__ k1, __half* __restrict__ v1,
    const __half* __restrict__ q2, const __half* __restrict__ k2, __half* __restrict__ v2)
{
    extern __shared__ uint32_t asmem[];
    uint32_t* sQ = asmem;            // 3 stages Q; later S (fp32, 4352 words)
    uint32_t* sK = asmem + 3 * QST;  // 3 stages K; later P (stage0) + V (1,2)

    const int tid = threadIdx.x, w = tid >> 5, lane = tid & 31;
    const int lr = lane >> 2, lc = lane & 3;
    const int wm = (w & 3) * 16;
    const int wn = (w >> 2) * 32;
    const size_t base = (size_t)blockIdx.x * (64 * 512);

    const __half *Q, *Kx;  __half* V;
    if (blockIdx.y == 0) { Q = q1; Kx = k2; V = v1; }
    else                 { Q = q2; Kx = k1; V = v2; }
    __half* O = V;

    const uint32_t qsm = (uint32_t)__cvta_generic_to_shared(sQ);
    const uint32_t ksm = (uint32_t)__cvta_generic_to_shared(sK);

    auto loadQK = [&](int st, int hc) {
#pragma unroll
        for (int i = 0; i < 2; i++) {
            int id = tid + i * 256;
            int r = id >> 3, q = id & 7;
            uint32_t off = (uint32_t)(st * QST + r * QW + q * 4) * 4;
            cpa16(qsm + off, Q  + base + (size_t)r * 512 + hc + q * 8);
            cpa16(ksm + off, Kx + base + (size_t)r * 512 + hc + q * 8);
        }
    };

    float sacc[4][4];
#pragma unroll
    for (int i = 0; i < 4; i++)
#pragma unroll
        for (int j = 0; j < 4; j++) sacc[i][j] = 0.f;

    // ---- Phase 1: S = Q @ K^T, 8 chunks of 64, 3-stage pipeline ----
    loadQK(0, 0);   cpa_commit();
    loadQK(1, 64);  cpa_commit();
    for (int c = 0; c < 8; c++) {
        cpa_wait<1>();
        __syncthreads();
        if (c + 2 < 8) loadQK((c + 2) % 3, (c + 2) * 64);
        cpa_commit();

        const uint32_t* qb = sQ + (c % 3) * QST;
        const uint32_t* kb = sK + (c % 3) * QST;
#pragma unroll
        for (int kk2 = 0; kk2 < 32; kk2 += 8) {
            uint32_t af[4];
            int r0 = wm + lr;
            af[0] = qb[r0 * QW + kk2 + lc];
            af[1] = qb[(r0 + 8) * QW + kk2 + lc];
            af[2] = qb[r0 * QW + kk2 + lc + 4];
            af[3] = qb[(r0 + 8) * QW + kk2 + lc + 4];
#pragma unroll
            for (int ni = 0; ni < 4; ni++) {
                int c0 = wn + ni * 8 + lr;
                uint32_t bf[2] = { kb[c0 * QW + kk2 + lc],
                                   kb[c0 * QW + kk2 + lc + 4] };
                mma16(sacc[ni], af, bf);
            }
        }
    }
    __syncthreads();   // all chunks done before S overwrites sQ

    // ---- dump S (fp32) into sQ ----
    float* S = reinterpret_cast<float*>(sQ);
#pragma unroll
    for (int ni = 0; ni < 4; ni++) {
        int row = wm + lr, col = wn + ni * 8 + lc * 2;
        S[row * SLD + col]           = sacc[ni][0];
        S[row * SLD + col + 1]       = sacc[ni][1];
        S[(row + 8) * SLD + col]     = sacc[ni][2];
        S[(row + 8) * SLD + col + 1] = sacc[ni][3];
    }
    __syncthreads();

    // ---- Phase 2: softmax (fp32), each warp owns 8 rows ----
    for (int r = w * 8; r < w * 8 + 8; r++) {
        float v0 = S[r * SLD + lane], v1 = S[r * SLD + 32 + lane];
        float m = fmaxf(v0, v1);
#pragma unroll
        for (int o = 16; o > 0; o >>= 1) m = fmaxf(m, __shfl_xor_sync(0xffffffffu, m, o));
        float e0 = __expf(v0 - m), e1 = __expf(v1 - m);
        float s = e0 + e1;
#pragma unroll
        for (int o = 16; o > 0; o >>= 1) s += __shfl_xor_sync(0xffffffffu, s, o);
        float inv = 1.f / s;
        S[r * SLD + lane]      = e0 * inv;
        S[r * SLD + 32 + lane] = e1 * inv;
    }
    __syncthreads();

    // ---- pack P (fp16 pair-words) into sK stage 0 ----
    uint32_t* Pw = sK;
    for (int idx = tid; idx < 64 * 32; idx += 256) {
        int row = idx >> 5, mp = idx & 31;
        Pw[row * QW + mp] = pk(S[row * SLD + 2 * mp], S[row * SLD + 2 * mp + 1]);
    }
    __syncthreads();

    // ---- hoist P fragments (reused for all 8 h-chunks) ----
    uint32_t paf[4][4];
#pragma unroll
    for (int c = 0; c < 4; c++) {
        int kk2 = c * 8, r0 = wm + lr;
        paf[c][0] = Pw[r0 * QW + kk2 + lc];
        paf[c][1] = Pw[(r0 + 8) * QW + kk2 + lc];
        paf[c][2] = Pw[r0 * QW + kk2 + lc + 4];
        paf[c][3] = Pw[(r0 + 8) * QW + kk2 + lc + 4];
    }
    __syncthreads();   // sK free for V stages

    // ---- Phase 3: O = P @ V, reg-pipelined V loads, 2-stage smem ----
    const int mp0 = tid >> 4, h40 = (tid & 15) * 4;                 // i = 0
    const int mp1 = (tid + 256) >> 4, h41 = ((tid + 256) & 15) * 4; // i = 1

    uint2 ra0, rb0, ra1, rb1;
    auto ldV = [&](int hc) {
        ra0 = *reinterpret_cast<const uint2*>(V + base + (size_t)(2 * mp0) * 512 + hc + h40);
        rb0 = *reinterpret_cast<const uint2*>(V + base + (size_t)(2 * mp0 + 1) * 512 + hc + h40);
        ra1 = *reinterpret_cast<const uint2*>(V + base + (size_t)(2 * mp1) * 512 + hc + h41);
        rb1 = *reinterpret_cast<const uint2*>(V + base + (size_t)(2 * mp1 + 1) * 512 + hc + h41);
    };
    ldV(0);

    for (int ci = 0; ci < 8; ci++) {
        int hc = ci * 64;
        uint32_t* vb = sK + (1 + (ci & 1)) * QST;   // stages 1,2
        *reinterpret_cast<uint4*>(&vb[mp0 * VW + h40]) =
            make_uint4(__byte_perm(ra0.x, rb0.x, 0x5410), __byte_perm(ra0.x, rb0.x, 0x7632),
                       __byte_perm(ra0.y, rb0.y, 0x5410), __byte_perm(ra0.y, rb0.y, 0x7632));
        *reinterpret_cast<uint4*>(&vb[mp1 * VW + h41]) =
            make_uint4(__byte_perm(ra1.x, rb1.x, 0x5410), __byte_perm(ra1.x, rb1.x, 0x7632),
                       __byte_perm(ra1.y, rb1.y, 0x5410), __byte_perm(ra1.y, rb1.y, 0x7632));
        __syncthreads();

        if (ci + 1 < 8) ldV(hc + 64);  // prefetch next chunk

        float oacc[4][4];
#pragma unroll
        for (int i = 0; i < 4; i++)
#pragma unroll
            for (int j = 0; j < 4; j++) oacc[i][j] = 0.f;
#pragma unroll
        for (int c = 0; c < 4; c++) {
            int kk2 = c * 8;
#pragma unroll
            for (int ni = 0; ni < 4; ni++) {
                int c0 = wn + ni * 8 + lr;
                uint32_t bf[2] = { vb[(kk2 + lc) * VW + c0],
                                   vb[(kk2 + lc + 4) * VW + c0] };
                mma16(oacc[ni], paf[c], bf);
            }
        }
#pragma unroll
        for (int ni = 0; ni < 4; ni++) {
            int row = wm + lr, col = wn + ni * 8 + lc * 2;
            st2(O + base + (size_t)row * 512 + hc + col,       oacc[ni][0], oacc[ni][1]);
            st2(O + base + (size_t)(row + 8) * 512 + hc + col, oacc[ni][2], oacc[ni][3]);
        }
    }
}

// ============================== launch ====================================
extern "C" void kernel_launch(void* const* d_in, const int* in_sizes, int n_in,
                              void* d_out, int out_size)
{
    const float* x1  = (const float*)d_in[0];
    const float* x2  = (const float*)d_in[1];
    const float* b1  = (const float*)d_in[9];
    const float* b2  = (const float*)d_in[11];
    float* out = (float*)d_out;

    __half* s;  uint32_t* wbase;
    cudaGetSymbolAddress((void**)&s, g_h);
    cudaGetSymbolAddress((void**)&wbase, g_w);

    __half* q1 = s + 0 * BUF;
    __half* k1 = s + 1 * BUF;
    __half* v1 = s + 2 * BUF;
    __half* q2 = s + 3 * BUF;
    __half* k2 = s + 4 * BUF;
    __half* v2 = s + 5 * BUF;
    __half* xh1 = s + 6 * BUF;
    __half* xh2 = xh1 + XBUF;
    __half* a1 = v1;   // attention output aliases V
    __half* a2 = v2;
    __half* h  = q1;   // MLP hidden reuses q1

    constexpr size_t WSZ = 128 * 512;
    uint32_t* wqkv = wbase;                   // 6 * WSZ (q1,k1,v1,q2,k2,v2 order)
    uint32_t* w1p  = wbase + 6 * WSZ;
    uint32_t* w2p  = w1p + 512 * 512;

    const float scale = 0.0625f;  // 256^-0.5
    dim3 blk(256);

    cudaFuncSetAttribute(gemm_p<__half, false, false, true >, cudaFuncAttributeMaxDynamicSharedMemorySize, (int)GEMM_SMEM);
    cudaFuncSetAttribute(gemm_p<__half, true,  true,  false>, cudaFuncAttributeMaxDynamicSharedMemorySize, (int)GEMM_SMEM);
    cudaFuncSetAttribute(gemm_p<float,  false, false, false>, cudaFuncAttributeMaxDynamicSharedMemorySize, (int)GEMM_SMEM);
    cudaFuncSetAttribute(attn_kernel, cudaFuncAttributeMaxDynamicSharedMemorySize, (int)ATTN_SMEM);

    // ---- pre-pass ----
    cvt_f2h<<<4096, 256>>>(x1, xh1, (int)(XBUF / 4));
    cvt_f2h<<<4096, 256>>>(x2, xh2, (int)(XBUF / 4));
    WSrc ws;
    ws.w[0] = (const float*)d_in[2];  // Wq1
    ws.w[1] = (const float*)d_in[3];  // Wk1
    ws.w[2] = (const float*)d_in[4];  // Wv1
    ws.w[3] = (const float*)d_in[5];  // Wq2
    ws.w[4] = (const float*)d_in[6];  // Wk2
    ws.w[5] = (const float*)d_in[7];  // Wv2
    ws.w[6] = (const float*)d_in[8];  // W1
    ws.w[7] = (const float*)d_in[10]; // W2
    pack_all<<<1024, 256>>>(ws, wbase);

    // ---- stage 1: all 6 projections in ONE launch (z: 0..5) ----
    dim3 gproj(4, MROWS / 128, 6);
    gemm_p<__half, false, false, true><<<gproj, blk, GEMM_SMEM>>>(
        xh1, xh2, wqkv, nullptr, q1, D_, 0, D_, WSZ, BUF, scale);

    // ---- stage 2: both cross attentions in ONE launch ----
    attn_kernel<<<dim3(BT, 2), blk, ATTN_SMEM>>>(q1, k1, v1, q2, k2, v2);

    // ---- stage 3: MLP ----
    dim3 gmlp(4, MROWS / 128, 1);
    gemm_p<__half, true, true, false><<<gmlp, blk, GEMM_SMEM>>>(
        a1, a2, w1p, b1, h, 2 * H_, H_, H_, 0, 0, 1.f);
    gemm_p<float, false, false, false><<<gmlp, blk, GEMM_SMEM>>>(
        h, nullptr, w2p, b2, out, H_, 0, H_, 0, 0, 1.f);
}

// round 8
// speedup vs baseline: 1.0920x; 1.0920x over previous
#include <cuda_runtime.h>
#include <cuda_fp16.h>
#include <cstdint>

// Problem constants
constexpr int B_ = 16, T_ = 128, N_ = 64, D_ = 256, H_ = 512;
constexpr int MROWS = B_ * T_ * N_;          // 131072 flattened rows
constexpr int BT   = B_ * T_;                // 2048 attention problems
constexpr size_t BUF  = (size_t)MROWS * H_;  // 67.1M elems (q/k/v buffers)
constexpr size_t XBUF = (size_t)MROWS * D_;  // fp16 copies of x

// ---------------- scratch (device globals) ---------------------------------
__device__ __align__(16) __half g_h[6 * BUF + 2 * XBUF];
// packed fp16x2 weights: wqkv1(3*65536) wqkv2(3*65536) w1p(262144) w2p(131072)
__device__ __align__(16) uint32_t g_w[786432];

__device__ __forceinline__ uint32_t pk(float a, float b) {
    __half2 h = __floats2half2_rn(a, b);
    return *reinterpret_cast<uint32_t*>(&h);
}
__device__ __forceinline__ void st2(float* p, float v0, float v1) {
    *reinterpret_cast<float2*>(p) = make_float2(v0, v1);
}
__device__ __forceinline__ void st2(__half* p, float v0, float v1) {
    *reinterpret_cast<__half2*>(p) = __floats2half2_rn(v0, v1);
}

// mma.sync m16n8k16 fp16 in / fp32 accum, D += A*B
__device__ __forceinline__ void mma16(float* d, const uint32_t* a, const uint32_t* b) {
    asm volatile(
        "mma.sync.aligned.m16n8k16.row.col.f32.f16.f16.f32 "
        "{%0,%1,%2,%3}, {%4,%5,%6,%7}, {%8,%9}, {%0,%1,%2,%3};"
        : "+f"(d[0]), "+f"(d[1]), "+f"(d[2]), "+f"(d[3])
        : "r"(a[0]), "r"(a[1]), "r"(a[2]), "r"(a[3]),
          "r"(b[0]), "r"(b[1]));
}

__device__ __forceinline__ void cpa16(uint32_t dst_smem, const void* src) {
    asm volatile("cp.async.cg.shared.global [%0], [%1], 16;" :: "r"(dst_smem), "l"(src));
}
__device__ __forceinline__ void cpa_commit() { asm volatile("cp.async.commit_group;"); }
template<int Ngrp> __device__ __forceinline__ void cpa_wait() {
    asm volatile("cp.async.wait_group %0;" :: "n"(Ngrp));
}

// ======================= conversion pre-pass ==============================
__global__ void cvt_f2h(const float* __restrict__ src, __half* __restrict__ dst, int n4) {
    for (int i = blockIdx.x * blockDim.x + threadIdx.x; i < n4; i += gridDim.x * blockDim.x) {
        float4 v = reinterpret_cast<const float4*>(src)[i];
        reinterpret_cast<uint2*>(dst)[i] = make_uint2(pk(v.x, v.y), pk(v.z, v.w));
    }
}
// Pack ALL weights in one launch. Regions (words): 6 x 65536, 262144, 131072.
struct WSrc { const float* w[8]; };
__global__ void pack_all(WSrc ws, uint32_t* __restrict__ out) {
    constexpr int R6 = 6 * 65536;           // 393216
    constexpr int R7 = R6 + 262144;         // 655360
    constexpr int TOT = R7 + 131072;        // 786432
    for (int i = blockIdx.x * blockDim.x + threadIdx.x; i < TOT; i += gridDim.x * blockDim.x) {
        const float* W; int local;
        if (i < R6)      { W = ws.w[i >> 16];  local = i & 65535; }
        else if (i < R7) { W = ws.w[6];        local = i - R6; }
        else             { W = ws.w[7];        local = i - R7; }
        int kp = local >> 9, n = local & 511;
        out[i] = pk(W[(size_t)(2 * kp) * 512 + n], W[(size_t)(2 * kp + 1) * 512 + n]);
    }
}

// =============================== GEMM =====================================
// C[M,512] = act( alpha * (A @ B) + bias ).  A fp16 row-major [M,K],
// B pre-packed u32 k-pair words [K/2][512].
// 128x128x64 tiles, 3-stage cp.async pipeline (prefetch distance 2),
// 256 thr, 8 warps (4m x 2n). __launch_bounds__(256,2) pins regs <= 128
// so 2 CTAs/SM fit the register file (R7 lesson: 136 regs -> 1 CTA/SM).
constexpr int AW = 36, BW = 136;          // smem strides (words)
constexpr int A_ST = 128 * AW;            // 4608 words
constexpr int B_ST = 32 * BW;             // 4352 words
constexpr int ST_W = A_ST + B_ST;         // 8960 words / stage
constexpr int NST = 3;
constexpr size_t GEMM_SMEM = (size_t)ST_W * NST * 4;   // 107520 B

template<typename TC, bool RELU, bool SPLITA, bool PROJ>
__global__ void __launch_bounds__(256, 2) gemm_p(
    const __half* __restrict__ A0, const __half* __restrict__ A1,
    const uint32_t* __restrict__ Bp, const float* __restrict__ bias,
    TC* __restrict__ C, int K, int ksplit, int lda,
    size_t bstride, size_t cstride, float alpha0)
{
    extern __shared__ uint32_t smem[];
    const uint32_t sm_base = (uint32_t)__cvta_generic_to_shared(smem);

    const int tid = threadIdx.x;
    const int bm  = blockIdx.y * 128;
    const int bn  = blockIdx.x * 128;
    const __half*   Az = PROJ ? (blockIdx.z < 3 ? A0 : A1) : A0;
    const uint32_t* Bz = Bp + (size_t)blockIdx.z * bstride;
    TC* Cz = C + (size_t)blockIdx.z * cstride;
    const float alpha = PROJ ? ((blockIdx.z % 3 == 0) ? alpha0 : 1.0f) : alpha0;

    const int w = tid >> 5, lane = tid & 31;
    const int wm = (w & 3) * 32, wn = (w >> 2) * 64;
    const int lr = lane >> 2, lc = lane & 3;

    float acc[2][8][4];
#pragma unroll
    for (int i = 0; i < 2; i++)
#pragma unroll
        for (int j = 0; j < 8; j++)
#pragma unroll
            for (int k = 0; k < 4; k++) acc[i][j][k] = 0.f;

    auto load_stage = [&](int s, int k0) {
        const __half* Ab = Az;
        int kl = k0;
        if (SPLITA && k0 >= ksplit) { Ab = A1; kl = k0 - ksplit; }
        uint32_t abase = sm_base + (uint32_t)(s * ST_W) * 4;
        uint32_t bbase = abase + (uint32_t)A_ST * 4;
#pragma unroll
        for (int i = 0; i < 4; i++) {
            int id = tid + i * 256;
            int r = id >> 3, q = id & 7;
            cpa16(abase + (uint32_t)(r * AW + q * 4) * 4,
                  Ab + (size_t)(bm + r) * lda + kl + q * 8);
        }
#pragma unroll
        for (int i = 0; i < 4; i++) {
            int id = tid + i * 256;
            int kp = id >> 5, j = id & 31;
            cpa16(bbase + (uint32_t)(kp * BW + j * 4) * 4,
                  Bz + (size_t)((k0 >> 1) + kp) * 512 + bn + j * 4);
        }
    };

    const int ntiles = K >> 6;
    load_stage(0, 0);  cpa_commit();
    if (ntiles > 1) load_stage(1, 64);
    cpa_commit();

    for (int t = 0; t < ntiles; t++) {
        cpa_wait<1>();
        __syncthreads();
        int tn = t + 2;
        if (tn < ntiles) load_stage(tn % NST, tn << 6);
        cpa_commit();

        const uint32_t* Ast = smem + (t % NST) * ST_W;
        const uint32_t* Bst = Ast + A_ST;
#pragma unroll
        for (int kk2 = 0; kk2 < 32; kk2 += 8) {
            uint32_t af[2][4];
#pragma unroll
            for (int mi = 0; mi < 2; mi++) {
                int r0 = wm + mi * 16 + lr;
                af[mi][0] = Ast[r0 * AW + kk2 + lc];
                af[mi][1] = Ast[(r0 + 8) * AW + kk2 + lc];
                af[mi][2] = Ast[r0 * AW + kk2 + lc + 4];
                af[mi][3] = Ast[(r0 + 8) * AW + kk2 + lc + 4];
            }
            uint32_t bf[8][2];
#pragma unroll
            for (int ni = 0; ni < 8; ni++) {
                int c0 = wn + ni * 8 + lr;
                bf[ni][0] = Bst[(kk2 + lc) * BW + c0];
                bf[ni][1] = Bst[(kk2 + lc + 4) * BW + c0];
            }
#pragma unroll
            for (int mi = 0; mi < 2; mi++)
#pragma unroll
                for (int ni = 0; ni < 8; ni++)
                    mma16(acc[mi][ni], af[mi], bf[ni]);
        }
        __syncthreads();
    }

#pragma unroll
    for (int mi = 0; mi < 2; mi++) {
#pragma unroll
        for (int ni = 0; ni < 8; ni++) {
            int row = bm + wm + mi * 16 + lr;
            int col = bn + wn + ni * 8 + lc * 2;
            float b0 = 0.f, b1 = 0.f;
            if (bias) { b0 = bias[col]; b1 = bias[col + 1]; }
            float v0 = acc[mi][ni][0] * alpha + b0;
            float v1 = acc[mi][ni][1] * alpha + b1;
            float v2 = acc[mi][ni][2] * alpha + b0;
            float v3 = acc[mi][ni][3] * alpha + b1;
            if (RELU) {
                v0 = fmaxf(v0, 0.f); v1 = fmaxf(v1, 0.f);
                v2 = fmaxf(v2, 0.f); v3 = fmaxf(v3, 0.f);
            }
            st2(Cz + (size_t)row * 512 + col, v0, v1);
            st2(Cz + (size_t)(row + 8) * 512 + col, v2, v3);
        }
    }
}

// ============================ Attention ===================================
// grid (2048, 2): y==0: a1 = softmax(q1 k2^T) v1 ; y==1: a2 = softmax(q2 k1^T) v2.
// O aliases V (per-column-chunk read-then-write, disjoint chunks).
// Phase 1: 3-stage cp.async Q/K chunk pipeline. Phase 3: reg-pipelined V LDG.
constexpr int QW = 36, SLD = 68, VW = 72;
constexpr int QST = 64 * QW;   // 2304 words / stage
constexpr size_t ATTN_SMEM = (size_t)6 * QST * 4;   // 55296 B

__global__ void __launch_bounds__(256, 2) attn_kernel(
    const __half* __restrict__ q1, const __half* __restrict__ k1, __half* __restrict__ v1,
    const __half* __restrict__ q2, const __half* __restrict__ k2, __half* __restrict__ v2)
{
    extern __shared__ uint32_t asmem[];
    uint32_t* sQ = asmem;            // 3 stages Q; later S (fp32, 4352 words)
    uint32_t* sK = asmem + 3 * QST;  // 3 stages K; later P (stage0) + V (1,2)

    const int tid = threadIdx.x, w = tid >> 5, lane = tid & 31;
    const int lr = lane >> 2, lc = lane & 3;
    const int wm = (w & 3) * 16;
    const int wn = (w >> 2) * 32;
    const size_t base = (size_t)blockIdx.x * (64 * 512);

    const __half *Q, *Kx;  __half* V;
    if (blockIdx.y == 0) { Q = q1; Kx = k2; V = v1; }
    else                 { Q = q2; Kx = k1; V = v2; }
    __half* O = V;

    const uint32_t qsm = (uint32_t)__cvta_generic_to_shared(sQ);
    const uint32_t ksm = (uint32_t)__cvta_generic_to_shared(sK);

    auto loadQK = [&](int st, int hc) {
#pragma unroll
        for (int i = 0; i < 2; i++) {
            int id = tid + i * 256;
            int r = id >> 3, q = id & 7;
            uint32_t off = (uint32_t)(st * QST + r * QW + q * 4) * 4;
            cpa16(qsm + off, Q  + base + (size_t)r * 512 + hc + q * 8);
            cpa16(ksm + off, Kx + base + (size_t)r * 512 + hc + q * 8);
        }
    };

    float sacc[4][4];
#pragma unroll
    for (int i = 0; i < 4; i++)
#pragma unroll
        for (int j = 0; j < 4; j++) sacc[i][j] = 0.f;

    // ---- Phase 1: S = Q @ K^T, 8 chunks of 64, 3-stage pipeline ----
    loadQK(0, 0);   cpa_commit();
    loadQK(1, 64);  cpa_commit();
    for (int c = 0; c < 8; c++) {
        cpa_wait<1>();
        __syncthreads();
        if (c + 2 < 8) loadQK((c + 2) % 3, (c + 2) * 64);
        cpa_commit();

        const uint32_t* qb = sQ + (c % 3) * QST;
        const uint32_t* kb = sK + (c % 3) * QST;
#pragma unroll
        for (int kk2 = 0; kk2 < 32; kk2 += 8) {
            uint32_t af[4];
            int r0 = wm + lr;
            af[0] = qb[r0 * QW + kk2 + lc];
            af[1] = qb[(r0 + 8) * QW + kk2 + lc];
            af[2] = qb[r0 * QW + kk2 + lc + 4];
            af[3] = qb[(r0 + 8) * QW + kk2 + lc + 4];
#pragma unroll
            for (int ni = 0; ni < 4; ni++) {
                int c0 = wn + ni * 8 + lr;
                uint32_t bf[2] = { kb[c0 * QW + kk2 + lc],
                                   kb[c0 * QW + kk2 + lc + 4] };
                mma16(sacc[ni], af, bf);
            }
        }
    }
    __syncthreads();   // all chunks done before S overwrites sQ

    // ---- dump S (fp32) into sQ ----
    float* S = reinterpret_cast<float*>(sQ);
#pragma unroll
    for (int ni = 0; ni < 4; ni++) {
        int row = wm + lr, col = wn + ni * 8 + lc * 2;
        S[row * SLD + col]           = sacc[ni][0];
        S[row * SLD + col + 1]       = sacc[ni][1];
        S[(row + 8) * SLD + col]     = sacc[ni][2];
        S[(row + 8) * SLD + col + 1] = sacc[ni][3];
    }
    __syncthreads();

    // ---- Phase 2: softmax (fp32), each warp owns 8 rows ----
    for (int r = w * 8; r < w * 8 + 8; r++) {
        float v0 = S[r * SLD + lane], v1 = S[r * SLD + 32 + lane];
        float m = fmaxf(v0, v1);
#pragma unroll
        for (int o = 16; o > 0; o >>= 1) m = fmaxf(m, __shfl_xor_sync(0xffffffffu, m, o));
        float e0 = __expf(v0 - m), e1 = __expf(v1 - m);
        float s = e0 + e1;
#pragma unroll
        for (int o = 16; o > 0; o >>= 1) s += __shfl_xor_sync(0xffffffffu, s, o);
        float inv = 1.f / s;
        S[r * SLD + lane]      = e0 * inv;
        S[r * SLD + 32 + lane] = e1 * inv;
    }
    __syncthreads();

    // ---- pack P (fp16 pair-words) into sK stage 0 ----
    uint32_t* Pw = sK;
    for (int idx = tid; idx < 64 * 32; idx += 256) {
        int row = idx >> 5, mp = idx & 31;
        Pw[row * QW + mp] = pk(S[row * SLD + 2 * mp], S[row * SLD + 2 * mp + 1]);
    }
    __syncthreads();

    // ---- hoist P fragments (reused for all 8 h-chunks) ----
    uint32_t paf[4][4];
#pragma unroll
    for (int c = 0; c < 4; c++) {
        int kk2 = c * 8, r0 = wm + lr;
        paf[c][0] = Pw[r0 * QW + kk2 + lc];
        paf[c][1] = Pw[(r0 + 8) * QW + kk2 + lc];
        paf[c][2] = Pw[r0 * QW + kk2 + lc + 4];
        paf[c][3] = Pw[(r0 + 8) * QW + kk2 + lc + 4];
    }
    __syncthreads();   // sK free for V stages

    // ---- Phase 3: O = P @ V, reg-pipelined V loads, 2-stage smem ----
    const int mp0 = tid >> 4, h40 = (tid & 15) * 4;                 // i = 0
    const int mp1 = (tid + 256) >> 4, h41 = ((tid + 256) & 15) * 4; // i = 1

    uint2 ra0, rb0, ra1, rb1;
    auto ldV = [&](int hc) {
        ra0 = *reinterpret_cast<const uint2*>(V + base + (size_t)(2 * mp0) * 512 + hc + h40);
        rb0 = *reinterpret_cast<const uint2*>(V + base + (size_t)(2 * mp0 + 1) * 512 + hc + h40);
        ra1 = *reinterpret_cast<const uint2*>(V + base + (size_t)(2 * mp1) * 512 + hc + h41);
        rb1 = *reinterpret_cast<const uint2*>(V + base + (size_t)(2 * mp1 + 1) * 512 + hc + h41);
    };
    ldV(0);

    for (int ci = 0; ci < 8; ci++) {
        int hc = ci * 64;
        uint32_t* vb = sK + (1 + (ci & 1)) * QST;   // stages 1,2
        *reinterpret_cast<uint4*>(&vb[mp0 * VW + h40]) =
            make_uint4(__byte_perm(ra0.x, rb0.x, 0x5410), __byte_perm(ra0.x, rb0.x, 0x7632),
                       __byte_perm(ra0.y, rb0.y, 0x5410), __byte_perm(ra0.y, rb0.y, 0x7632));
        *reinterpret_cast<uint4*>(&vb[mp1 * VW + h41]) =
            make_uint4(__byte_perm(ra1.x, rb1.x, 0x5410), __byte_perm(ra1.x, rb1.x, 0x7632),
                       __byte_perm(ra1.y, rb1.y, 0x5410), __byte_perm(ra1.y, rb1.y, 0x7632));
        __syncthreads();

        if (ci + 1 < 8) ldV(hc + 64);  // prefetch next chunk

        float oacc[4][4];
#pragma unroll
        for (int i = 0; i < 4; i++)
#pragma unroll
            for (int j = 0; j < 4; j++) oacc[i][j] = 0.f;
#pragma unroll
        for (int c = 0; c < 4; c++) {
            int kk2 = c * 8;
#pragma unroll
            for (int ni = 0; ni < 4; ni++) {
                int c0 = wn + ni * 8 + lr;
                uint32_t bf[2] = { vb[(kk2 + lc) * VW + c0],
                                   vb[(kk2 + lc + 4) * VW + c0] };
                mma16(oacc[ni], paf[c], bf);
            }
        }
#pragma unroll
        for (int ni = 0; ni < 4; ni++) {
            int row = wm + lr, col = wn + ni * 8 + lc * 2;
            st2(O + base + (size_t)row * 512 + hc + col,       oacc[ni][0], oacc[ni][1]);
            st2(O + base + (size_t)(row + 8) * 512 + hc + col, oacc[ni][2], oacc[ni][3]);
        }
    }
}

// ============================== launch ====================================
extern "C" void kernel_launch(void* const* d_in, const int* in_sizes, int n_in,
                              void* d_out, int out_size)
{
    const float* x1  = (const float*)d_in[0];
    const float* x2  = (const float*)d_in[1];
    const float* b1  = (const float*)d_in[9];
    const float* b2  = (const float*)d_in[11];
    float* out = (float*)d_out;

    __half* s;  uint32_t* wbase;
    cudaGetSymbolAddress((void**)&s, g_h);
    cudaGetSymbolAddress((void**)&wbase, g_w);

    __half* q1 = s + 0 * BUF;
    __half* k1 = s + 1 * BUF;
    __half* v1 = s + 2 * BUF;
    __half* q2 = s + 3 * BUF;
    __half* k2 = s + 4 * BUF;
    __half* v2 = s + 5 * BUF;
    __half* xh1 = s + 6 * BUF;
    __half* xh2 = xh1 + XBUF;
    __half* a1 = v1;   // attention output aliases V
    __half* a2 = v2;
    __half* h  = q1;   // MLP hidden reuses q1

    constexpr size_t WSZ = 128 * 512;
    uint32_t* wqkv = wbase;                   // 6 * WSZ (q1,k1,v1,q2,k2,v2 order)
    uint32_t* w1p  = wbase + 6 * WSZ;
    uint32_t* w2p  = w1p + 512 * 512;

    const float scale = 0.0625f;  // 256^-0.5
    dim3 blk(256);

    cudaFuncSetAttribute(gemm_p<__half, false, false, true >, cudaFuncAttributeMaxDynamicSharedMemorySize, (int)GEMM_SMEM);
    cudaFuncSetAttribute(gemm_p<__half, true,  true,  false>, cudaFuncAttributeMaxDynamicSharedMemorySize, (int)GEMM_SMEM);
    cudaFuncSetAttribute(gemm_p<float,  false, false, false>, cudaFuncAttributeMaxDynamicSharedMemorySize, (int)GEMM_SMEM);
    cudaFuncSetAttribute(attn_kernel, cudaFuncAttributeMaxDynamicSharedMemorySize, (int)ATTN_SMEM);

    // ---- pre-pass ----
    cvt_f2h<<<4096, 256>>>(x1, xh1, (int)(XBUF / 4));
    cvt_f2h<<<4096, 256>>>(x2, xh2, (int)(XBUF / 4));
    WSrc ws;
    ws.w[0] = (const float*)d_in[2];  // Wq1
    ws.w[1] = (const float*)d_in[3];  // Wk1
    ws.w[2] = (const float*)d_in[4];  // Wv1
    ws.w[3] = (const float*)d_in[5];  // Wq2
    ws.w[4] = (const float*)d_in[6];  // Wk2
    ws.w[5] = (const float*)d_in[7];  // Wv2
    ws.w[6] = (const float*)d_in[8];  // W1
    ws.w[7] = (const float*)d_in[10]; // W2
    pack_all<<<1024, 256>>>(ws, wbase);

    // ---- stage 1: all 6 projections in ONE launch (z: 0..5) ----
    dim3 gproj(4, MROWS / 128, 6);
    gemm_p<__half, false, false, true><<<gproj, blk, GEMM_SMEM>>>(
        xh1, xh2, wqkv, nullptr, q1, D_, 0, D_, WSZ, BUF, scale);

    // ---- stage 2: both cross attentions in ONE launch ----
    attn_kernel<<<dim3(BT, 2), blk, ATTN_SMEM>>>(q1, k1, v1, q2, k2, v2);

    // ---- stage 3: MLP ----
    dim3 gmlp(4, MROWS / 128, 1);
    gemm_p<__half, true, true, false><<<gmlp, blk, GEMM_SMEM>>>(
        a1, a2, w1p, b1, h, 2 * H_, H_, H_, 0, 0, 1.f);
    gemm_p<float, false, false, false><<<gmlp, blk, GEMM_SMEM>>>(
        h, nullptr, w2p, b2, out, H_, 0, H_, 0, 0, 1.f);
}